// round 17
// baseline (speedup 1.0000x reference)
#include <cuda_runtime.h>
#include <math.h>

#define H 2048
#define FOURH 8192
#define NT 256   // threads per block

// Scratch — h outputs (layers 0,1) + partial gates for layers 1,2
__device__ __align__(16) float g_h[2 * H];
__device__ __align__(16) float g_pg[2 * FOURH];
__device__ int g_c1, g_f1, g_w2, g_done;   // zero at load; self-reset each run

__device__ __forceinline__ float sigmoidf_(float x) { return 1.0f / (1.0f + expf(-x)); }

__device__ __forceinline__ float warp_red(float v) {
    #pragma unroll
    for (int o = 16; o > 0; o >>= 1) v += __shfl_xor_sync(0xffffffffu, v, o);
    return v;
}
__device__ __forceinline__ float d4(float4 a, float4 b) {
    return a.x * b.x + a.y * b.y + a.z * b.z + a.w * b.w;
}

// 4 dot products: rows {j, j+H, j+2H, j+3H} of W [4H x H] vs h [H].
// All 8 W loads issued back-to-back into distinct registers BEFORE any FMA.
__device__ __forceinline__ void dot4(const float* __restrict__ W, int j,
                                     const float* __restrict__ h, float s[4]) {
    const int t = threadIdx.x;
    const float4* h4 = reinterpret_cast<const float4*>(h);
    const float4* r0 = reinterpret_cast<const float4*>(W) + (size_t)(0 * H + j) * 512;
    const float4* r1 = reinterpret_cast<const float4*>(W) + (size_t)(1 * H + j) * 512;
    const float4* r2 = reinterpret_cast<const float4*>(W) + (size_t)(2 * H + j) * 512;
    const float4* r3 = reinterpret_cast<const float4*>(W) + (size_t)(3 * H + j) * 512;

    float4 a0 = __ldcs(r0 + t);
    float4 a1 = __ldcs(r1 + t);
    float4 a2 = __ldcs(r2 + t);
    float4 a3 = __ldcs(r3 + t);
    float4 b0 = __ldcs(r0 + t + NT);
    float4 b1 = __ldcs(r1 + t + NT);
    float4 b2 = __ldcs(r2 + t + NT);
    float4 b3 = __ldcs(r3 + t + NT);
    float4 hv0 = __ldg(h4 + t);
    float4 hv1 = __ldg(h4 + t + NT);

    s[0] = d4(a0, hv0) + d4(b0, hv1);
    s[1] = d4(a1, hv0) + d4(b1, hv1);
    s[2] = d4(a2, hv0) + d4(b2, hv1);
    s[3] = d4(a3, hv0) + d4(b3, hv1);
}

// Variant for dependent (finish) blocks: issue the 8 W loads FIRST, then spin
// on readiness counters, then consume. Weight traffic stays in flight during
// the (short) spin window.
struct WBatch { float4 a0, a1, a2, a3, b0, b1, b2, b3; };

__device__ __forceinline__ void issue_w(const float* __restrict__ W, int j, WBatch& wb) {
    const int t = threadIdx.x;
    const float4* r0 = reinterpret_cast<const float4*>(W) + (size_t)(0 * H + j) * 512;
    const float4* r1 = reinterpret_cast<const float4*>(W) + (size_t)(1 * H + j) * 512;
    const float4* r2 = reinterpret_cast<const float4*>(W) + (size_t)(2 * H + j) * 512;
    const float4* r3 = reinterpret_cast<const float4*>(W) + (size_t)(3 * H + j) * 512;
    wb.a0 = __ldcs(r0 + t);
    wb.a1 = __ldcs(r1 + t);
    wb.a2 = __ldcs(r2 + t);
    wb.a3 = __ldcs(r3 + t);
    wb.b0 = __ldcs(r0 + t + NT);
    wb.b1 = __ldcs(r1 + t + NT);
    wb.b2 = __ldcs(r2 + t + NT);
    wb.b3 = __ldcs(r3 + t + NT);
}
__device__ __forceinline__ void finish_dot(const WBatch& wb, const float* __restrict__ h,
                                           float s[4]) {
    const int t = threadIdx.x;
    const float4* h4 = reinterpret_cast<const float4*>(h);
    float4 hv0 = __ldcg(h4 + t);
    float4 hv1 = __ldcg(h4 + t + NT);
    s[0] = d4(wb.a0, hv0) + d4(wb.b0, hv1);
    s[1] = d4(wb.a1, hv0) + d4(wb.b1, hv1);
    s[2] = d4(wb.a2, hv0) + d4(wb.b2, hv1);
    s[3] = d4(wb.a3, hv0) + d4(wb.b3, hv1);
}

__device__ __forceinline__ void reduce4(float s[4], float tot[4]) {
    __shared__ float sm[NT / 32][4];
    const int lane = threadIdx.x & 31;
    const int w = threadIdx.x >> 5;
    #pragma unroll
    for (int g = 0; g < 4; g++) s[g] = warp_red(s[g]);
    if (lane == 0) {
        #pragma unroll
        for (int g = 0; g < 4; g++) sm[w][g] = s[g];
    }
    __syncthreads();
    if (threadIdx.x == 0) {
        #pragma unroll
        for (int g = 0; g < 4; g++) {
            float v = 0.0f;
            #pragma unroll
            for (int ww = 0; ww < NT / 32; ww++) v += sm[ww][g];
            tot[g] = v;
        }
    }
}

// K1 (4096 blocks): [0,2048) layer0 full epilogue; [2048,4096) Whh1 partial.
// Counter g_c1 counts ALL K1 blocks; trigger at block end (safe PDL).
__global__ void __launch_bounds__(NT) k1(
    const float* __restrict__ x,
    const float* __restrict__ hid,
    const float* __restrict__ cell,
    const float* __restrict__ Wih0,
    const float* __restrict__ Whh0,
    const float* __restrict__ bih0, const float* __restrict__ bhh0,
    const float* __restrict__ Whh1,
    const float* __restrict__ bih1, const float* __restrict__ bhh1,
    const float* __restrict__ bout,
    float* __restrict__ out)
{
    const int b = blockIdx.x;
    const int layer = b >> 11;
    const int j = b & (H - 1);

    if (b == 0 && threadIdx.x == 32) out[0] = bout[0];

    const float* W = (layer == 0) ? Whh0 : Whh1;
    const float* h = hid + layer * H;

    float s[4];
    dot4(W, j, h, s);
    float tot[4];
    reduce4(s, tot);

    if (threadIdx.x == 0) {
        if (layer == 0) {
            const float xv = x[0];
            float gate[4];
            #pragma unroll
            for (int g = 0; g < 4; g++) {
                int r = g * H + j;
                gate[g] = tot[g] + xv * Wih0[r] + bih0[r] + bhh0[r];
            }
            float c2 = sigmoidf_(gate[1]) * cell[j] + sigmoidf_(gate[0]) * tanhf(gate[2]);
            float h2 = sigmoidf_(gate[3]) * tanhf(c2);
            g_h[j] = h2;
            out[1 + j] = h2;
            out[1 + 3 * H + j] = c2;
        } else {
            #pragma unroll
            for (int g = 0; g < 4; g++) {
                int r = g * H + j;
                g_pg[r] = tot[g] + bih1[r] + bhh1[r];
            }
        }
        __threadfence();
        atomicAdd(&g_c1, 1);
    }
#if __CUDA_ARCH__ >= 900
    cudaTriggerProgrammaticLaunchCompletion();
#endif
}

// K2 (4096 blocks, PDL secondary): bids [0,2048) = Whh2 partial (NO dependency
// on K1 — fills K1's drain window); bids [2048,4096) = finish layer 1
// (front-issue Wih1 loads, spin g_c1, consume).
__global__ void __launch_bounds__(NT) k2(
    const float* __restrict__ hid,
    const float* __restrict__ cell,
    const float* __restrict__ Wih1,
    const float* __restrict__ Whh2,
    const float* __restrict__ bih2, const float* __restrict__ bhh2,
    float* __restrict__ out)
{
    const int b = blockIdx.x;
    if (b < H) {
        const int j = b;
        float s[4];
        dot4(Whh2, j, hid + 2 * H, s);
        float tot[4];
        reduce4(s, tot);
        if (threadIdx.x == 0) {
            #pragma unroll
            for (int g = 0; g < 4; g++) {
                int r = g * H + j;
                g_pg[FOURH + r] = tot[g] + bih2[r] + bhh2[r];
            }
            __threadfence();
            atomicAdd(&g_w2, 1);
        }
    } else {
        const int j = b - H;
        WBatch wb;
        issue_w(Wih1, j, wb);                 // weight traffic in flight pre-spin
        if (threadIdx.x == 0) {
            while (*(volatile int*)&g_c1 < 2 * H) __nanosleep(64);
        }
        __syncthreads();
        __threadfence();
        float s[4];
        finish_dot(wb, g_h, s);
        float tot[4];
        reduce4(s, tot);
        if (threadIdx.x == 0) {
            float gate[4];
            #pragma unroll
            for (int g = 0; g < 4; g++) gate[g] = tot[g] + __ldcg(&g_pg[g * H + j]);
            float c2 = sigmoidf_(gate[1]) * cell[H + j] + sigmoidf_(gate[0]) * tanhf(gate[2]);
            float h2 = sigmoidf_(gate[3]) * tanhf(c2);
            g_h[H + j] = h2;
            out[1 + H + j] = h2;
            out[1 + 4 * H + j] = c2;
            __threadfence();
            atomicAdd(&g_f1, 1);
        }
    }
#if __CUDA_ARCH__ >= 900
    cudaTriggerProgrammaticLaunchCompletion();
#endif
}

// K3 (2048 blocks, PDL secondary): finish layer 2 + output projection.
// Front-issue Wih2 loads, spin on finish1 + Whh2 counters, consume.
// Last block resets all sync state for the next graph replay.
__global__ void __launch_bounds__(NT) k3(
    const float* __restrict__ Wih2,
    const float* __restrict__ cell,
    const float* __restrict__ Wout,
    float* __restrict__ out)
{
    const int j = blockIdx.x;
    WBatch wb;
    issue_w(Wih2, j, wb);
    if (threadIdx.x == 0) {
        while (*(volatile int*)&g_f1 < H || *(volatile int*)&g_w2 < H) __nanosleep(64);
    }
    __syncthreads();
    __threadfence();
    float s[4];
    finish_dot(wb, g_h + H, s);
    float tot[4];
    reduce4(s, tot);

    if (threadIdx.x == 0) {
        float gate[4];
        #pragma unroll
        for (int g = 0; g < 4; g++) gate[g] = tot[g] + __ldcg(&g_pg[FOURH + g * H + j]);
        float c2 = sigmoidf_(gate[1]) * cell[2 * H + j] + sigmoidf_(gate[0]) * tanhf(gate[2]);
        float h2 = sigmoidf_(gate[3]) * tanhf(c2);
        out[1 + 2 * H + j] = h2;
        out[1 + 5 * H + j] = c2;
        atomicAdd(&out[0], h2 * __ldg(&Wout[j]));
        int v = atomicAdd(&g_done, 1);
        if (v == H - 1) {
            g_c1 = 0; g_f1 = 0; g_w2 = 0; g_done = 0;
            __threadfence();
        }
    }
}

extern "C" void kernel_launch(void* const* d_in, const int* in_sizes, int n_in,
                              void* d_out, int out_size) {
    const float* x    = (const float*)d_in[0];
    const float* hid  = (const float*)d_in[1];
    const float* cell = (const float*)d_in[2];
    const float* Wih0 = (const float*)d_in[3];
    const float* Whh0 = (const float*)d_in[4];
    const float* bih0 = (const float*)d_in[5];
    const float* bhh0 = (const float*)d_in[6];
    const float* Wih1 = (const float*)d_in[7];
    const float* Whh1 = (const float*)d_in[8];
    const float* bih1 = (const float*)d_in[9];
    const float* bhh1 = (const float*)d_in[10];
    const float* Wih2 = (const float*)d_in[11];
    const float* Whh2 = (const float*)d_in[12];
    const float* bih2 = (const float*)d_in[13];
    const float* bhh2 = (const float*)d_in[14];
    const float* Wout = (const float*)d_in[15];
    const float* bout = (const float*)d_in[16];
    float* out = (float*)d_out;

    k1<<<2 * H, NT>>>(x, hid, cell, Wih0,
                      Whh0, bih0, bhh0,
                      Whh1, bih1, bhh1, bout, out);

    cudaLaunchAttribute attrs[1];
    attrs[0].id = cudaLaunchAttributeProgrammaticStreamSerialization;
    attrs[0].val.programmaticStreamSerializationAllowed = 1;

    cudaLaunchConfig_t cfg2 = {};
    cfg2.gridDim = dim3(2 * H);
    cfg2.blockDim = dim3(NT);
    cfg2.stream = 0;
    cfg2.attrs = attrs;
    cfg2.numAttrs = 1;
    cudaLaunchKernelEx(&cfg2, k2, hid, cell, Wih1, Whh2, bih2, bhh2, out);

    cudaLaunchConfig_t cfg3 = cfg2;
    cfg3.gridDim = dim3(H);
    cudaLaunchKernelEx(&cfg3, k3, Wih2, cell, Wout, out);
}